// round 8
// baseline (speedup 1.0000x reference)
#include <cuda_runtime.h>
#include <math.h>

#define NB   16
#define SL   128
#define NN   2048
#define DIN  256
#define DE   192
#define HH   256
#define LOUT 12
#define NLEV 21

__device__ float g_x[NN * DIN];
__device__ float g_proj[NN * 4 * HH];
__device__ float g_h[NN * HH];
__device__ float g_c[NN * HH];
__device__ int   g_off[NB][SL + 1];
__device__ int   g_child[NB][SL];

__device__ __forceinline__ float sg(float v) { return 1.0f / (1.0f + __expf(-v)); }

// ---------------- gather: x = concat(emb_W[xs], rel_W[rels]) ----------------
__global__ void k_gather(const int* __restrict__ xs, const int* __restrict__ rels,
                         const float* __restrict__ embW, const float* __restrict__ relW) {
    int n = blockIdx.x;
    int t = threadIdx.x;  // 64 threads
    const float* e = embW + (long long)xs[n] * DE;
    const float* r = relW + (long long)rels[n] * 64;
    for (int i = t; i < DIN; i += 64)
        g_x[n * DIN + i] = (i < DE) ? e[i] : r[i - DE];
}

// ---------------- CSR build (per tree, sequential, deterministic) ----------------
__global__ void k_setup(const int* __restrict__ parent) {
    int b = blockIdx.x;
    if (threadIdx.x != 0) return;
    int deg[SL];
    for (int i = 0; i < SL; i++) deg[i] = 0;
    for (int e = 0; e < SL - 1; e++) deg[parent[b * (SL - 1) + e] - b * SL]++;
    int o = 0;
    for (int i = 0; i < SL; i++) { g_off[b][i] = o; o += deg[i]; deg[i] = g_off[b][i]; }
    g_off[b][SL] = o;
    for (int e = 0; e < SL - 1; e++) {
        int p = parent[b * (SL - 1) + e] - b * SL;
        g_child[b][deg[p]++] = b * SL + e + 1;   // child of edge e is node e+1
    }
}

// ---------------- projections GEMM: g_proj[n][m*256+h] = x[n] @ W_m (+bias) ----------------
// blockIdx.x: node tile (64 nodes), blockIdx.y: column tile (64 cols of virtual 1024-wide W)
__global__ void k_proj(const float* __restrict__ Wix, const float* __restrict__ Wfx,
                       const float* __restrict__ Wox, const float* __restrict__ Wux,
                       const float* __restrict__ bix, const float* __restrict__ bih,
                       const float* __restrict__ bfx, const float* __restrict__ bfh) {
    __shared__ float As[16][65];
    __shared__ float Bs[16][64];
    int n0 = blockIdx.x * 64;
    int j0 = blockIdx.y * 64;
    int m = j0 >> 8;
    int h0 = j0 & 255;
    const float* W = (m == 0) ? Wix : (m == 1) ? Wfx : (m == 2) ? Wox : Wux;
    int t = threadIdx.x;
    int tx = t & 15, ty = t >> 4;
    float acc[4][4];
#pragma unroll
    for (int i = 0; i < 4; i++)
#pragma unroll
        for (int j = 0; j < 4; j++) acc[i][j] = 0.0f;

    for (int k0 = 0; k0 < DIN; k0 += 16) {
        for (int e = t; e < 1024; e += 256) {
            int nl = e >> 4, kk = e & 15;
            As[kk][nl] = g_x[(n0 + nl) * DIN + k0 + kk];
        }
        for (int e = t; e < 1024; e += 256) {
            int kk = e >> 6, c = e & 63;
            Bs[kk][c] = W[(k0 + kk) * HH + h0 + c];
        }
        __syncthreads();
#pragma unroll
        for (int kk = 0; kk < 16; kk++) {
            float a0 = As[kk][tx * 4 + 0], a1 = As[kk][tx * 4 + 1];
            float a2 = As[kk][tx * 4 + 2], a3 = As[kk][tx * 4 + 3];
            float b0 = Bs[kk][ty * 4 + 0], b1 = Bs[kk][ty * 4 + 1];
            float b2 = Bs[kk][ty * 4 + 2], b3 = Bs[kk][ty * 4 + 3];
            acc[0][0] += a0 * b0; acc[0][1] += a0 * b1; acc[0][2] += a0 * b2; acc[0][3] += a0 * b3;
            acc[1][0] += a1 * b0; acc[1][1] += a1 * b1; acc[1][2] += a1 * b2; acc[1][3] += a1 * b3;
            acc[2][0] += a2 * b0; acc[2][1] += a2 * b1; acc[2][2] += a2 * b2; acc[2][3] += a2 * b3;
            acc[3][0] += a3 * b0; acc[3][1] += a3 * b1; acc[3][2] += a3 * b2; acc[3][3] += a3 * b3;
        }
        __syncthreads();
    }
#pragma unroll
    for (int jj = 0; jj < 4; jj++) {
        int h = h0 + ty * 4 + jj;
        float bias = (m == 0) ? (bix[h] + bih[h]) : (m == 1) ? (bfx[h] + bfh[h]) : 0.0f;
        int j = j0 + ty * 4 + jj;
#pragma unroll
        for (int i = 0; i < 4; i++)
            g_proj[(n0 + tx * 4 + i) * 1024 + j] = acc[i][jj] + bias;
    }
}

// ---------------- one level of the tree LSTM ----------------
// grid (2048, 4): block handles node blockIdx.x, channels [blockIdx.y*64, +64), 64 threads.
__global__ void k_level(int level, const int* __restrict__ height,
                        const float* __restrict__ Wih, const float* __restrict__ Wfh,
                        const float* __restrict__ Woh, const float* __restrict__ Wuh) {
    int n = blockIdx.x;
    if (height[n] != level) return;
    int lt = threadIdx.x;
    int t = lt + (blockIdx.y << 6);
    const float* pr = g_proj + (long long)n * 1024;
    float ixv = pr[t], fxv = pr[256 + t], oxv = pr[512 + t], uxv = pr[768 + t];
    int b = n >> 7, loc = n & 127;
    int beg = g_off[b][loc], end = g_off[b][loc + 1];

    if (beg == end) {  // leaf: h_sum=0, fc=0
        float i = sg(ixv), o = sg(oxv), u = tanhf(uxv);
        float c = i * u;
        g_c[n * HH + t] = c;
        g_h[n * HH + t] = o * tanhf(c);
        return;
    }

    __shared__ float s_h[HH];
    __shared__ float s_hs[HH];
#pragma unroll
    for (int j = 0; j < 4; j++) s_hs[lt + j * 64] = 0.0f;

    float fc = 0.0f;
    for (int e = beg; e < end; e++) {
        int c = g_child[b][e];
        __syncthreads();
#pragma unroll
        for (int j = 0; j < 4; j++) s_h[lt + j * 64] = g_h[c * HH + lt + j * 64];
        float cc = g_c[c * HH + t];
        __syncthreads();
#pragma unroll
        for (int j = 0; j < 4; j++) s_hs[lt + j * 64] += s_h[lt + j * 64];
        float a = 0.0f;
#pragma unroll 8
        for (int d = 0; d < HH; d++) a += s_h[d] * Wfh[d * HH + t];
        fc += sg(a + fxv) * cc;
    }
    __syncthreads();

    float ai = 0.0f, ao = 0.0f, au = 0.0f;
#pragma unroll 4
    for (int d = 0; d < HH; d++) {
        float hv = s_hs[d];
        ai += hv * Wih[d * HH + t];
        ao += hv * Woh[d * HH + t];
        au += hv * Wuh[d * HH + t];
    }
    float i = sg(ixv + ai), o = sg(oxv + ao), u = tanhf(uxv + au);
    float cn = i * u + fc;
    g_c[n * HH + t] = cn;
    g_h[n * HH + t] = o * tanhf(cn);
}

// ---------------- max-pool over sequence + output projection ----------------
__global__ void k_out(const float* __restrict__ Wout, const float* __restrict__ bout,
                      float* __restrict__ out) {
    int b = blockIdx.x;
    int t = threadIdx.x;  // 256
    __shared__ float pool[HH];
    float m = -1e30f;
    for (int s = 0; s < SL; s++) m = fmaxf(m, g_h[(b * SL + s) * HH + t]);
    pool[t] = m;
    __syncthreads();
    if (t < LOUT) {
        float a = bout[t];
#pragma unroll 8
        for (int d = 0; d < HH; d++) a += pool[d] * Wout[d * LOUT + t];
        out[b * LOUT + t] = a;
    }
}

extern "C" void kernel_launch(void* const* d_in, const int* in_sizes, int n_in,
                              void* d_out, int out_size) {
    const int* xs     = (const int*)d_in[0];
    const int* rels   = (const int*)d_in[1];
    const int* parent = (const int*)d_in[3];   // d_in[2] (child_idx) derivable, unused
    const int* height = (const int*)d_in[4];
    int base = (in_sizes[5] == 1) ? 6 : 5;     // skip n_levels scalar if present
    const float* embW = (const float*)d_in[base + 0];
    const float* relW = (const float*)d_in[base + 1];
    const float* Wix  = (const float*)d_in[base + 2];
    const float* bix  = (const float*)d_in[base + 3];
    const float* Wih  = (const float*)d_in[base + 4];
    const float* bih  = (const float*)d_in[base + 5];
    const float* Wfx  = (const float*)d_in[base + 6];
    const float* bfx  = (const float*)d_in[base + 7];
    const float* Wfh  = (const float*)d_in[base + 8];
    const float* bfh  = (const float*)d_in[base + 9];
    const float* Wox  = (const float*)d_in[base + 10];
    const float* Woh  = (const float*)d_in[base + 11];
    const float* Wux  = (const float*)d_in[base + 12];
    const float* Wuh  = (const float*)d_in[base + 13];
    const float* Wout = (const float*)d_in[base + 14];
    const float* bout = (const float*)d_in[base + 15];
    float* out = (float*)d_out;

    k_gather<<<NN, 64>>>(xs, rels, embW, relW);
    k_setup<<<NB, 32>>>(parent);
    dim3 gp(NN / 64, 1024 / 64);
    k_proj<<<gp, 256>>>(Wix, Wfx, Wox, Wux, bix, bih, bfx, bfh);
    for (int lv = 0; lv < NLEV; lv++)
        k_level<<<dim3(NN, 4), 64>>>(lv, height, Wih, Wfh, Woh, Wuh);
    k_out<<<NB, 256>>>(Wout, bout, out);
}

// round 10
// speedup vs baseline: 2.9695x; 2.9695x over previous
#include <cuda_runtime.h>
#include <math.h>

#define NB   16
#define SL   128
#define NN   2048
#define HH   256
#define LOUT 12
#define NLEV 21
#define GRID 128

__device__ float g_x[NN * 256];
__device__ float g_proj[NN * 1024];
__device__ float g_h[NN * HH];
__device__ float g_c[NN * HH];
__device__ int   g_coff[NB][SL + 1];
__device__ int   g_cch[NB][SL];
__device__ int   g_loff[NB][NLEV + 2];
__device__ int   g_lnode[NB][SL];
__device__ unsigned g_tbar[NB][NLEV + 1];
__device__ unsigned g_gbar[4];

__device__ __forceinline__ float sg(float v) { return 1.0f / (1.0f + __expf(-v)); }

__device__ __forceinline__ void bar_sig(unsigned* p) {
    unsigned long long ga;
    asm("cvta.to.global.u64 %0, %1;" : "=l"(ga) : "l"(p));
    asm volatile("red.release.gpu.global.add.u32 [%0], 1;" :: "l"(ga) : "memory");
}
__device__ __forceinline__ void bar_spin(unsigned* p, unsigned tgt) {
    unsigned long long ga;
    asm("cvta.to.global.u64 %0, %1;" : "=l"(ga) : "l"(p));
    unsigned v;
    do {
        asm volatile("ld.acquire.gpu.global.u32 %0, [%1];" : "=r"(v) : "l"(ga) : "memory");
    } while (v < tgt);
}

__global__ void k_zero() {
    int t = threadIdx.x;
    if (t < NB * (NLEV + 1)) ((unsigned*)g_tbar)[t] = 0u;
    if (t < 4) g_gbar[t] = 0u;
}

__global__ void __launch_bounds__(256) k_main(
    const int* __restrict__ xs, const int* __restrict__ rels,
    const int* __restrict__ parent, const int* __restrict__ height,
    const float* __restrict__ embW, const float* __restrict__ relW,
    const float* __restrict__ Wix, const float* __restrict__ bix,
    const float* __restrict__ Wih, const float* __restrict__ bih,
    const float* __restrict__ Wfx, const float* __restrict__ bfx,
    const float* __restrict__ Wfh, const float* __restrict__ bfh,
    const float* __restrict__ Wox, const float* __restrict__ Woh,
    const float* __restrict__ Wux, const float* __restrict__ Wuh,
    const float* __restrict__ Wout, const float* __restrict__ bout,
    float* __restrict__ out)
{
    __shared__ __align__(16) char sraw[16640];
    int tid = threadIdx.x;
    int bx = blockIdx.x;

    // ================= phase 1: gather x = concat(emb[xs], rel[rels]) =================
    for (int idx = tid; idx < 16 * 256; idx += 256) {
        int nl = idx >> 8, d = idx & 255;
        int n = bx * 16 + nl;
        float v = (d < 192) ? embW[(long long)xs[n] * 192 + d]
                            : relW[(long long)rels[n] * 64 + (d - 192)];
        g_x[n * 256 + d] = v;
    }

    // ================= phase 2: setup (blocks 0..15, deterministic) =================
    if (bx < NB) {
        int b = bx;
        int* spar  = (int*)sraw;          // [128] (127 used)
        int* shgt  = spar + 128;          // [128]
        int* soff  = shgt + 128;          // [129]
        int* sloff = soff + 129;          // [23]
        if (tid < 127) spar[tid] = parent[b * 127 + tid] - b * 128;
        if (tid < 128) shgt[tid] = height[b * 128 + tid];
        __syncthreads();
        if (tid < 128) {                   // degree of node tid
            int d = 0;
            for (int e = 0; e < 127; e++) d += (spar[e] == tid);
            soff[tid] = d;
        }
        __syncthreads();
        if (tid == 0) {                    // exclusive scan -> CSR offsets
            int acc = 0;
            for (int i = 0; i < 128; i++) {
                int d = soff[i]; soff[i] = acc; g_coff[b][i] = acc; acc += d;
            }
            soff[128] = acc; g_coff[b][128] = acc;
        }
        __syncthreads();
        if (tid < 128) {                   // children in edge order (deterministic)
            int k = soff[tid];
            for (int e = 0; e < 127; e++)
                if (spar[e] == tid) g_cch[b][k++] = e + 1;
        }
        if (tid <= NLEV) {                 // per-level node counts
            int c = 0;
            for (int i = 0; i < 128; i++) c += (shgt[i] == tid);
            sloff[tid] = c;
        }
        __syncthreads();
        if (tid == 0) {
            int acc = 0;
            for (int l = 0; l <= NLEV; l++) {
                int c = sloff[l]; sloff[l] = acc; g_loff[b][l] = acc; acc += c;
            }
            g_loff[b][NLEV + 1] = acc;
        }
        __syncthreads();
        if (tid < 128) {                   // stable placement by node id
            int h = shgt[tid];
            int rank = 0;
            for (int i = 0; i < tid; i++) rank += (shgt[i] == h);
            g_lnode[b][sloff[h] + rank] = tid;
        }
    }
    // ---- grid barrier 0 ----
    __syncthreads();
    if (tid == 0) { bar_sig(&g_gbar[0]); bar_spin(&g_gbar[0], GRID); }
    __syncthreads();

    // ================= phase 3: projections GEMM =================
    {
        float* As = (float*)sraw;          // [16][65]
        float* Bs = As + 16 * 65;          // [16][64]
        int tx = tid & 15, ty = tid >> 4;
        for (int tile = bx; tile < 512; tile += GRID) {
            int n0 = (tile & 31) * 64;
            int j0 = (tile >> 5) * 64;
            int m = j0 >> 8, h0 = j0 & 255;
            const float* W = (m == 0) ? Wix : (m == 1) ? Wfx : (m == 2) ? Wox : Wux;
            float acc[4][4];
#pragma unroll
            for (int i = 0; i < 4; i++)
#pragma unroll
                for (int j = 0; j < 4; j++) acc[i][j] = 0.0f;
            for (int k0 = 0; k0 < 256; k0 += 16) {
                for (int e = tid; e < 1024; e += 256) {
                    int nl = e >> 4, kk = e & 15;
                    As[kk * 65 + nl] = g_x[(n0 + nl) * 256 + k0 + kk];
                }
                for (int e = tid; e < 1024; e += 256) {
                    int kk = e >> 6, c = e & 63;
                    Bs[kk * 64 + c] = W[(k0 + kk) * 256 + h0 + c];
                }
                __syncthreads();
#pragma unroll
                for (int kk = 0; kk < 16; kk++) {
                    float a0 = As[kk * 65 + tx * 4 + 0], a1 = As[kk * 65 + tx * 4 + 1];
                    float a2 = As[kk * 65 + tx * 4 + 2], a3 = As[kk * 65 + tx * 4 + 3];
                    float b0 = Bs[kk * 64 + ty * 4 + 0], b1 = Bs[kk * 64 + ty * 4 + 1];
                    float b2 = Bs[kk * 64 + ty * 4 + 2], b3 = Bs[kk * 64 + ty * 4 + 3];
                    acc[0][0] += a0 * b0; acc[0][1] += a0 * b1; acc[0][2] += a0 * b2; acc[0][3] += a0 * b3;
                    acc[1][0] += a1 * b0; acc[1][1] += a1 * b1; acc[1][2] += a1 * b2; acc[1][3] += a1 * b3;
                    acc[2][0] += a2 * b0; acc[2][1] += a2 * b1; acc[2][2] += a2 * b2; acc[2][3] += a2 * b3;
                    acc[3][0] += a3 * b0; acc[3][1] += a3 * b1; acc[3][2] += a3 * b2; acc[3][3] += a3 * b3;
                }
                __syncthreads();
            }
#pragma unroll
            for (int jj = 0; jj < 4; jj++) {
                int h = h0 + ty * 4 + jj;
                float bias = (m == 0) ? (bix[h] + bih[h]) : (m == 1) ? (bfx[h] + bfh[h]) : 0.0f;
                int j = j0 + ty * 4 + jj;
#pragma unroll
                for (int i = 0; i < 4; i++)
                    g_proj[(n0 + tx * 4 + i) * 1024 + j] = acc[i][jj] + bias;
            }
        }
    }
    // ---- grid barrier 1 ----
    __syncthreads();
    if (tid == 0) { bar_sig(&g_gbar[1]); bar_spin(&g_gbar[1], GRID); }
    __syncthreads();

    // ================= phase 4: tree LSTM (8 CTAs per tree, 32 channels each) ========
    {
        int b = bx >> 3, q = bx & 7, ch0 = q * 32;
        int w = tid >> 5, l = tid & 31;
        int ch = ch0 + l;
        float* hbuf = ((float*)sraw) + w * 260;         // per-warp child-h buffer
        float* hsm  = ((float*)sraw) + 8 * 260 + w * 260;

        // level 0: leaves (elementwise)
        {
            int lb = g_loff[b][0], le = g_loff[b][1];
            for (int li = lb + w; li < le; li += 8) {
                int n = (b << 7) + g_lnode[b][li];
                const float* pr = g_proj + (size_t)n * 1024;
                float i = sg(pr[ch]), o = sg(pr[512 + ch]), u = tanhf(pr[768 + ch]);
                float c = i * u;
                g_c[(size_t)n * 256 + ch] = c;
                g_h[(size_t)n * 256 + ch] = o * tanhf(c);
            }
        }
        for (int L = 1; L <= 20; L++) {
            // per-tree barrier: level L-1 writes visible to all 8 CTAs
            __syncthreads();
            if (tid == 0) { bar_sig(&g_tbar[b][L - 1]); bar_spin(&g_tbar[b][L - 1], 8u); }
            __syncthreads();
            int nb_ = g_loff[b][L], ne_ = g_loff[b][L + 1];
            for (int ni = nb_ + w; ni < ne_; ni += 8) {
                int loc = g_lnode[b][ni];
                int n = (b << 7) + loc;
                int beg = g_coff[b][loc], end = g_coff[b][loc + 1];
                const float* pr = g_proj + (size_t)n * 1024;
                float ixv = pr[ch], fxv = pr[256 + ch], oxv = pr[512 + ch], uxv = pr[768 + ch];
                float hs0 = 0, hs1 = 0, hs2 = 0, hs3 = 0, hs4 = 0, hs5 = 0, hs6 = 0, hs7 = 0;
                float fc = 0.0f;
                for (int e = beg; e < end; e++) {
                    int c = (b << 7) + g_cch[b][e];
                    const float4* hp = (const float4*)(g_h + (size_t)c * 256);
                    float4 ha = hp[l * 2], hb4 = hp[l * 2 + 1];
                    *(float4*)(hbuf + l * 8)     = ha;
                    *(float4*)(hbuf + l * 8 + 4) = hb4;
                    hs0 += ha.x; hs1 += ha.y; hs2 += ha.z; hs3 += ha.w;
                    hs4 += hb4.x; hs5 += hb4.y; hs6 += hb4.z; hs7 += hb4.w;
                    float cc = g_c[(size_t)c * 256 + ch];
                    __syncwarp();
                    float a = 0.0f;
#pragma unroll 8
                    for (int d = 0; d < 256; d += 4) {
                        float4 h4 = *(const float4*)(hbuf + d);
                        a = fmaf(h4.x, Wfh[(d + 0) * 256 + ch], a);
                        a = fmaf(h4.y, Wfh[(d + 1) * 256 + ch], a);
                        a = fmaf(h4.z, Wfh[(d + 2) * 256 + ch], a);
                        a = fmaf(h4.w, Wfh[(d + 3) * 256 + ch], a);
                    }
                    fc = fmaf(sg(a + fxv), cc, fc);
                    __syncwarp();
                }
                *(float4*)(hsm + l * 8)     = make_float4(hs0, hs1, hs2, hs3);
                *(float4*)(hsm + l * 8 + 4) = make_float4(hs4, hs5, hs6, hs7);
                __syncwarp();
                float ai = 0.0f, ao = 0.0f, au = 0.0f;
#pragma unroll 4
                for (int d = 0; d < 256; d += 4) {
                    float4 h4 = *(const float4*)(hsm + d);
                    ai = fmaf(h4.x, Wih[(d + 0) * 256 + ch], ai);
                    ao = fmaf(h4.x, Woh[(d + 0) * 256 + ch], ao);
                    au = fmaf(h4.x, Wuh[(d + 0) * 256 + ch], au);
                    ai = fmaf(h4.y, Wih[(d + 1) * 256 + ch], ai);
                    ao = fmaf(h4.y, Woh[(d + 1) * 256 + ch], ao);
                    au = fmaf(h4.y, Wuh[(d + 1) * 256 + ch], au);
                    ai = fmaf(h4.z, Wih[(d + 2) * 256 + ch], ai);
                    ao = fmaf(h4.z, Woh[(d + 2) * 256 + ch], ao);
                    au = fmaf(h4.z, Wuh[(d + 2) * 256 + ch], au);
                    ai = fmaf(h4.w, Wih[(d + 3) * 256 + ch], ai);
                    ao = fmaf(h4.w, Woh[(d + 3) * 256 + ch], ao);
                    au = fmaf(h4.w, Wuh[(d + 3) * 256 + ch], au);
                }
                float i = sg(ixv + ai), o = sg(oxv + ao), u = tanhf(uxv + au);
                float cn = fmaf(i, u, fc);
                g_c[(size_t)n * 256 + ch] = cn;
                g_h[(size_t)n * 256 + ch] = o * tanhf(cn);
                __syncwarp();   // hsm reads done before next node overwrites
            }
        }
        // final per-tree barrier, then fused pool + output proj (CTA q==0)
        __syncthreads();
        if (tid == 0) { bar_sig(&g_tbar[b][20]); bar_spin(&g_tbar[b][20], 8u); }
        __syncthreads();
        if (q == 0) {
            float* pool = (float*)sraw;
            float m = -1e30f;
            const float* hp = g_h + (size_t)(b << 7) * 256 + tid;
#pragma unroll 4
            for (int s = 0; s < 128; s++) m = fmaxf(m, hp[s * 256]);
            pool[tid] = m;
            __syncthreads();
            if (tid < LOUT) {
                float a = bout[tid];
#pragma unroll 8
                for (int d = 0; d < 256; d++) a = fmaf(pool[d], Wout[d * LOUT + tid], a);
                out[b * LOUT + tid] = a;
            }
        }
    }
}

extern "C" void kernel_launch(void* const* d_in, const int* in_sizes, int n_in,
                              void* d_out, int out_size) {
    const int* xs     = (const int*)d_in[0];
    const int* rels   = (const int*)d_in[1];
    const int* parent = (const int*)d_in[3];
    const int* height = (const int*)d_in[4];
    int base = (in_sizes[5] == 1) ? 6 : 5;
    const float* embW = (const float*)d_in[base + 0];
    const float* relW = (const float*)d_in[base + 1];
    const float* Wix  = (const float*)d_in[base + 2];
    const float* bix  = (const float*)d_in[base + 3];
    const float* Wih  = (const float*)d_in[base + 4];
    const float* bih  = (const float*)d_in[base + 5];
    const float* Wfx  = (const float*)d_in[base + 6];
    const float* bfx  = (const float*)d_in[base + 7];
    const float* Wfh  = (const float*)d_in[base + 8];
    const float* bfh  = (const float*)d_in[base + 9];
    const float* Wox  = (const float*)d_in[base + 10];
    const float* Woh  = (const float*)d_in[base + 11];
    const float* Wux  = (const float*)d_in[base + 12];
    const float* Wuh  = (const float*)d_in[base + 13];
    const float* Wout = (const float*)d_in[base + 14];
    const float* bout = (const float*)d_in[base + 15];
    float* out = (float*)d_out;

    k_zero<<<1, 512>>>();
    k_main<<<GRID, 256>>>(xs, rels, parent, height, embW, relW,
                          Wix, bix, Wih, bih, Wfx, bfx, Wfh, bfh,
                          Wox, Woh, Wux, Wuh, Wout, bout, out);
}